// round 5
// baseline (speedup 1.0000x reference)
#include <cuda_runtime.h>
#include <cuda_fp16.h>
#include <math.h>
#include <stdint.h>

// ---------------- problem constants ----------------
static constexpr int Bn   = 1024;
static constexpr int M3   = 3072;   // B*S
static constexpr int Dd   = 256;
static constexpr int SD   = 768;
static constexpr int OUT1 = 512;
static constexpr int LAT  = 128;

static constexpr size_t N_BE  = (size_t)Bn * 1024;
static constexpr size_t N_BSD = (size_t)M3 * Dd;     // 786432

__device__ float g_scratch[2 * N_BE + 22 * N_BSD + (size_t)Bn * OUT1];
__device__ float g_bias_fused[512];            // [0:256)=b4+b5, [256:512)=b6+b7
__device__ __half g_Wh[16777216];              // bil_W in fp16 (32MB)

__device__ __forceinline__ float sigm(float x) { return 1.0f / (1.0f + expf(-x)); }

__device__ __forceinline__ unsigned tf32r(float x) {
    unsigned r;
    asm("cvt.rna.tf32.f32 %0, %1;" : "=r"(r) : "f"(x));
    return r;
}

__device__ __forceinline__ void mma_tf32(float& c0, float& c1, float& c2, float& c3,
                                         unsigned a0, unsigned a1, unsigned a2, unsigned a3,
                                         unsigned b0, unsigned b1) {
    asm("mma.sync.aligned.m16n8k8.row.col.f32.tf32.tf32.f32 "
        "{%0,%1,%2,%3}, {%4,%5,%6,%7}, {%8,%9}, {%0,%1,%2,%3};"
        : "+f"(c0), "+f"(c1), "+f"(c2), "+f"(c3)
        : "r"(a0), "r"(a1), "r"(a2), "r"(a3), "r"(b0), "r"(b1));
}

__device__ __forceinline__ void mma_f16(float& c0, float& c1, float& c2, float& c3,
                                        unsigned a0, unsigned a1, unsigned a2, unsigned a3,
                                        unsigned b0, unsigned b1) {
    asm("mma.sync.aligned.m16n8k16.row.col.f32.f16.f16.f32 "
        "{%0,%1,%2,%3}, {%4,%5,%6,%7}, {%8,%9}, {%0,%1,%2,%3};"
        : "+f"(c0), "+f"(c1), "+f"(c2), "+f"(c3)
        : "r"(a0), "r"(a1), "r"(a2), "r"(a3), "r"(b0), "r"(b1));
}

// ---------------- helpers ----------------
__global__ void fuse_bias_kernel(const float* __restrict__ b, float* __restrict__ o)
{
    int i = threadIdx.x;
    o[i]       = b[4 * 256 + i] + b[5 * 256 + i];
    o[256 + i] = b[6 * 256 + i] + b[7 * 256 + i];
}

// bilW fp32 -> fp16 (once per launch; deterministic)
__global__ void wconv_kernel(const float* __restrict__ W, __half* __restrict__ Wh)
{
    size_t i = ((size_t)blockIdx.x * 256 + threadIdx.x) * 4;
    float4 v = *(const float4*)(W + i);
    __half2 h0 = __floats2half2_rn(v.x, v.y);
    __half2 h1 = __floats2half2_rn(v.z, v.w);
    *(__half2*)(Wh + i)     = h0;
    *(__half2*)(Wh + i + 2) = h1;
}

// ---------------- fp32 SIMT GEMM (precision-critical encoder/multiscale layers) ----------
#define BM 64
#define BN 64
#define BK 16

__global__ void __launch_bounds__(256) gemm_kernel(
    const float* __restrict__ A, const float* __restrict__ W,
    const float* __restrict__ bias, float* __restrict__ C,
    int M, int N, int K, int flags)
{
    __shared__ __align__(16) float As[BK][BM + 4];
    __shared__ __align__(16) float Ws[BK][BN + 4];
    const int tid = threadIdx.x;
    const int tx = tid & 15, ty = tid >> 4;
    const int m0 = blockIdx.y * BM, n0 = blockIdx.x * BN;
    const int lm = tid >> 2;
    const int lk = (tid & 3) << 2;
    const float* Ag = A + (size_t)(m0 + lm) * K + lk;
    const float* Wg = W + (size_t)(n0 + lm) * K + lk;

    float acc[4][4] = {};
    for (int kt = 0; kt < K; kt += BK) {
        float4 av = *(const float4*)(Ag + kt);
        float4 wv = *(const float4*)(Wg + kt);
        As[lk + 0][lm] = av.x; As[lk + 1][lm] = av.y;
        As[lk + 2][lm] = av.z; As[lk + 3][lm] = av.w;
        Ws[lk + 0][lm] = wv.x; Ws[lk + 1][lm] = wv.y;
        Ws[lk + 2][lm] = wv.z; Ws[lk + 3][lm] = wv.w;
        __syncthreads();
#pragma unroll
        for (int k = 0; k < BK; k++) {
            float4 a = *(const float4*)&As[k][ty << 2];
            float4 b = *(const float4*)&Ws[k][tx << 2];
            acc[0][0] = fmaf(a.x, b.x, acc[0][0]); acc[0][1] = fmaf(a.x, b.y, acc[0][1]);
            acc[0][2] = fmaf(a.x, b.z, acc[0][2]); acc[0][3] = fmaf(a.x, b.w, acc[0][3]);
            acc[1][0] = fmaf(a.y, b.x, acc[1][0]); acc[1][1] = fmaf(a.y, b.y, acc[1][1]);
            acc[1][2] = fmaf(a.y, b.z, acc[1][2]); acc[1][3] = fmaf(a.y, b.w, acc[1][3]);
            acc[2][0] = fmaf(a.z, b.x, acc[2][0]); acc[2][1] = fmaf(a.z, b.y, acc[2][1]);
            acc[2][2] = fmaf(a.z, b.z, acc[2][2]); acc[2][3] = fmaf(a.z, b.w, acc[2][3]);
            acc[3][0] = fmaf(a.w, b.x, acc[3][0]); acc[3][1] = fmaf(a.w, b.y, acc[3][1]);
            acc[3][2] = fmaf(a.w, b.z, acc[3][2]); acc[3][3] = fmaf(a.w, b.w, acc[3][3]);
        }
        __syncthreads();
    }
#pragma unroll
    for (int i = 0; i < 4; i++) {
#pragma unroll
        for (int j = 0; j < 4; j++) {
            int row = m0 + (ty << 2) + i;
            int col = n0 + (tx << 2) + j;
            float v = acc[i][j] + bias[col];
            if (flags & 1) v = fmaxf(v, 0.0f);
            C[(size_t)row * N + col] = v;
        }
    }
}

// ---------------- tf32 tensor GEMM: K-split or N-split weights + fused epilogue -------
// flags: bit0 relu ; bit2 sigmul: out = sigm(v * E[row*eld + eoff + col]) ; bit3 N-split
// K-split (bit3=0): Wcat row n = [W[n,0:Kx] | W2[n,0:K-Kx]]
// N-split (bit3=1): rows n<Kx from W (bias), rows >=Kx from W2 (bias2); both [.,K]
__global__ void __launch_bounds__(128) mma_gemm_kernel(
    const float* __restrict__ A, const float* __restrict__ W, const float* __restrict__ W2,
    const float* __restrict__ bias, const float* __restrict__ bias2, float* __restrict__ C,
    int M, int N, int K, int Kx, int flags,
    const float* __restrict__ E, int eld, int eoff)
{
    __shared__ float As[16][72];
    __shared__ float Ws[16][72];
    const int tid = threadIdx.x;
    const int lane = tid & 31, wid = tid >> 5;
    const int wm = wid >> 1, wn = wid & 1;
    const int m0 = blockIdx.y * 64, n0 = blockIdx.x * 64;
    const int c4 = lane & 3, lr = lane >> 2;
    const int Kb = K - Kx;
    const bool nsplit = (flags & 8) != 0;

    float c[2][4][4];
#pragma unroll
    for (int mt = 0; mt < 2; mt++)
#pragma unroll
        for (int nt = 0; nt < 4; nt++)
#pragma unroll
            for (int e = 0; e < 4; e++) c[mt][nt][e] = 0.0f;

    const int lrow = tid >> 2, lsq = tid & 3;
    float4 pa[2], pw[2];
    {
        int k = lsq * 4;
#pragma unroll
        for (int u = 0; u < 2; u++) {
            int row = lrow + u * 32;
            pa[u] = *(const float4*)(A + (size_t)(m0 + row) * K + k);
            const float* ws;
            if (nsplit) {
                int n = n0 + row;
                ws = (n < Kx) ? (W + (size_t)n * K + k) : (W2 + (size_t)(n - Kx) * K + k);
            } else {
                ws = (k < Kx) ? (W + (size_t)(n0 + row) * Kx + k)
                              : (W2 + (size_t)(n0 + row) * Kb + (k - Kx));
            }
            pw[u] = *(const float4*)ws;
        }
    }

    const int ktiles = K >> 4;
    for (int kt = 0; kt < ktiles; kt++) {
#pragma unroll
        for (int u = 0; u < 2; u++) {
            int row = lrow + u * 32;
            As[lsq * 4 + 0][row] = __uint_as_float(tf32r(pa[u].x));
            As[lsq * 4 + 1][row] = __uint_as_float(tf32r(pa[u].y));
            As[lsq * 4 + 2][row] = __uint_as_float(tf32r(pa[u].z));
            As[lsq * 4 + 3][row] = __uint_as_float(tf32r(pa[u].w));
            Ws[lsq * 4 + 0][row] = __uint_as_float(tf32r(pw[u].x));
            Ws[lsq * 4 + 1][row] = __uint_as_float(tf32r(pw[u].y));
            Ws[lsq * 4 + 2][row] = __uint_as_float(tf32r(pw[u].z));
            Ws[lsq * 4 + 3][row] = __uint_as_float(tf32r(pw[u].w));
        }
        __syncthreads();
        if (kt + 1 < ktiles) {
            int k = (kt + 1) * 16 + lsq * 4;
#pragma unroll
            for (int u = 0; u < 2; u++) {
                int row = lrow + u * 32;
                pa[u] = *(const float4*)(A + (size_t)(m0 + row) * K + k);
                const float* ws;
                if (nsplit) {
                    int n = n0 + row;
                    ws = (n < Kx) ? (W + (size_t)n * K + k) : (W2 + (size_t)(n - Kx) * K + k);
                } else {
                    ws = (k < Kx) ? (W + (size_t)(n0 + row) * Kx + k)
                                  : (W2 + (size_t)(n0 + row) * Kb + (k - Kx));
                }
                pw[u] = *(const float4*)ws;
            }
        }
#pragma unroll
        for (int kk = 0; kk < 16; kk += 8) {
            unsigned a[2][4];
#pragma unroll
            for (int mt = 0; mt < 2; mt++) {
                int rb = wm * 32 + mt * 16 + lr;
                a[mt][0] = __float_as_uint(As[kk + c4][rb]);
                a[mt][1] = __float_as_uint(As[kk + c4][rb + 8]);
                a[mt][2] = __float_as_uint(As[kk + c4 + 4][rb]);
                a[mt][3] = __float_as_uint(As[kk + c4 + 4][rb + 8]);
            }
#pragma unroll
            for (int nt = 0; nt < 4; nt++) {
                int nb = wn * 32 + nt * 8 + lr;
                unsigned b0 = __float_as_uint(Ws[kk + c4][nb]);
                unsigned b1 = __float_as_uint(Ws[kk + c4 + 4][nb]);
#pragma unroll
                for (int mt = 0; mt < 2; mt++)
                    mma_tf32(c[mt][nt][0], c[mt][nt][1], c[mt][nt][2], c[mt][nt][3],
                             a[mt][0], a[mt][1], a[mt][2], a[mt][3], b0, b1);
            }
        }
        __syncthreads();
    }

#pragma unroll
    for (int mt = 0; mt < 2; mt++) {
#pragma unroll
        for (int nt = 0; nt < 4; nt++) {
            int row = m0 + wm * 32 + mt * 16 + lr;
            int col = n0 + wn * 32 + nt * 8 + c4 * 2;
#pragma unroll
            for (int e = 0; e < 4; e++) {
                int rr = row + (e >> 1) * 8;
                int cc = col + (e & 1);
                float bv = nsplit ? ((cc < Kx) ? bias[cc] : bias2[cc - Kx]) : bias[cc];
                float v = c[mt][nt][e] + bv;
                if (flags & 1) v = fmaxf(v, 0.0f);
                if (flags & 4) v = sigm(v * E[(size_t)rr * eld + eoff + cc]);
                C[(size_t)rr * N + cc] = v;
            }
        }
    }
}

// ---------------- fp16 bilinear v2: cp.async W (fp16 gmem), 2-rounding E ----------------
// part[ks][r][o] = sum_{i in ks-range, j} cva[r,i] W[o,i,j] cav[r,j]
// grid (48, 2, 4): r-block 64, o-block 128, i-range 64. 256 threads = 8 warps (2m x 4n).
// smem: s_cav [64][264] fp16 ; s_W [2][128][72] fp16  (total 70656 B)
static constexpr int BIL2_SMEM_BYTES = (64 * 264 + 2 * 128 * 72) * 2;

__global__ void __launch_bounds__(256) bilinear2_kernel(
    const float* __restrict__ cva, const float* __restrict__ cav,
    const __half* __restrict__ Wh, float* __restrict__ part)
{
    extern __shared__ __half sh[];
    __half* s_cav = sh;               // [64][264]
    __half* s_W   = sh + 64 * 264;    // [2][128][72]

    const int tid = threadIdx.x;
    const int lane = tid & 31, wid = tid >> 5;
    const int wm = wid >> 2, wn = wid & 3;
    const int g = lane >> 2, q = lane & 3;
    const int r0 = blockIdx.x * 64, o0 = blockIdx.y * 128;
    const int iBase = blockIdx.z * 64;

    // load cav rows -> fp16 smem (single rounding of cav)
    for (int f = tid; f < 4096; f += 256) {
        int row = f >> 6, q4 = f & 63;
        float4 w = *(const float4*)(cav + (size_t)(r0 + row) * 256 + q4 * 4);
        __half* d = s_cav + row * 264 + q4 * 4;
        *(__half2*)(d)     = __floats2half2_rn(w.x, w.y);
        *(__half2*)(d + 2) = __floats2half2_rn(w.z, w.w);
    }

    float c[2][4][4];
#pragma unroll
    for (int mt = 0; mt < 2; mt++)
#pragma unroll
        for (int nt = 0; nt < 4; nt++)
#pragma unroll
            for (int e = 0; e < 4; e++) c[mt][nt][e] = 0.0f;

    // cp.async W tile loader: per it -> 128 o x 64 j halves = 16KB = 1024 x 16B chunks
    const int co = tid >> 1;                  // base o for chunks (with +128 stride below)
    auto issue_tile = [&](int it) {
        int i = iBase + (it >> 2), h = it & 3;
        __half* dst0 = s_W + (it & 1) * 128 * 72;
#pragma unroll
        for (int u = 0; u < 4; u++) {
            int cidx = tid + 256 * u;          // 0..1023
            int o = cidx >> 3, ch = cidx & 7;  // o: 0..127, ch: 0..7 (8 halves each)
            const __half* src = Wh + (size_t)(o0 + o) * 65536 + (size_t)i * 256 + h * 64 + ch * 8;
            unsigned sa = (unsigned)__cvta_generic_to_shared(dst0 + o * 72 + ch * 8);
            asm volatile("cp.async.cg.shared.global [%0], [%1], 16;" :: "r"(sa), "l"(src));
        }
        asm volatile("cp.async.commit_group;");
    };
    (void)co;

    issue_tile(0);
    __syncthreads();   // s_cav ready

    const int rbase = wm * 32 + g;
    const float* cvaB = cva + (size_t)(r0 + rbase) * 256;

    for (int it = 0; it < 256; it++) {
        if (it + 1 < 256) {
            issue_tile(it + 1);
            asm volatile("cp.async.wait_group 1;");
        } else {
            asm volatile("cp.async.wait_group 0;");
        }
        __syncthreads();   // tile(it) visible to all threads

        const __half* wbuf = s_W + (it & 1) * 128 * 72;
        const int ig = iBase + (it >> 2);
        const int h = it & 3;
        // fp32 cva scalars (L1-broadcast LDG) -- no pre-rounding of cva
        float s0 = cvaB[ig];
        float s1 = cvaB[8 * 256 + ig];
        float s2 = cvaB[16 * 256 + ig];
        float s3 = cvaB[24 * 256 + ig];

#pragma unroll
        for (int jc = 0; jc < 4; jc++) {
            const int jlo = h * 64 + jc * 16 + 2 * q;
            const int jhi = jlo + 8;
            __half2 a[2][4];
            {
                float2 f;
                f = __half22float2(*(__half2*)&s_cav[(rbase)      * 264 + jlo]);
                a[0][0] = __floats2half2_rn(s0 * f.x, s0 * f.y);
                f = __half22float2(*(__half2*)&s_cav[(rbase + 8)  * 264 + jlo]);
                a[0][1] = __floats2half2_rn(s1 * f.x, s1 * f.y);
                f = __half22float2(*(__half2*)&s_cav[(rbase)      * 264 + jhi]);
                a[0][2] = __floats2half2_rn(s0 * f.x, s0 * f.y);
                f = __half22float2(*(__half2*)&s_cav[(rbase + 8)  * 264 + jhi]);
                a[0][3] = __floats2half2_rn(s1 * f.x, s1 * f.y);
                f = __half22float2(*(__half2*)&s_cav[(rbase + 16) * 264 + jlo]);
                a[1][0] = __floats2half2_rn(s2 * f.x, s2 * f.y);
                f = __half22float2(*(__half2*)&s_cav[(rbase + 24) * 264 + jlo]);
                a[1][1] = __floats2half2_rn(s3 * f.x, s3 * f.y);
                f = __half22float2(*(__half2*)&s_cav[(rbase + 16) * 264 + jhi]);
                a[1][2] = __floats2half2_rn(s2 * f.x, s2 * f.y);
                f = __half22float2(*(__half2*)&s_cav[(rbase + 24) * 264 + jhi]);
                a[1][3] = __floats2half2_rn(s3 * f.x, s3 * f.y);
            }
            const int kloc = jc * 16;
#pragma unroll
            for (int nt = 0; nt < 4; nt++) {
                int oc = wn * 32 + nt * 8 + g;
                unsigned b0 = *(const unsigned*)&wbuf[oc * 72 + kloc + 2 * q];
                unsigned b1 = *(const unsigned*)&wbuf[oc * 72 + kloc + 2 * q + 8];
#pragma unroll
                for (int mt = 0; mt < 2; mt++)
                    mma_f16(c[mt][nt][0], c[mt][nt][1], c[mt][nt][2], c[mt][nt][3],
                            *(unsigned*)&a[mt][0], *(unsigned*)&a[mt][1],
                            *(unsigned*)&a[mt][2], *(unsigned*)&a[mt][3], b0, b1);
            }
        }
        __syncthreads();   // done reading this buffer before it is re-filled
    }

    float* P = part + (size_t)blockIdx.z * N_BSD;
#pragma unroll
    for (int mt = 0; mt < 2; mt++) {
#pragma unroll
        for (int nt = 0; nt < 4; nt++) {
            int row = r0 + wm * 32 + mt * 16 + g;
            int col = o0 + wn * 32 + nt * 8 + q * 2;
            float* d0 = P + (size_t)row * 256 + col;
            float* d1 = P + (size_t)(row + 8) * 256 + col;
            d0[0] = c[mt][nt][0]; d0[1] = c[mt][nt][1];
            d1[0] = c[mt][nt][2]; d1[1] = c[mt][nt][3];
        }
    }
}

// finish: j = sigm(sum partials); m = tc*j*xv + (1-j)*xa; o1 = m*mv; o2 = m*ma
__global__ void bil_finish_kernel(const float* __restrict__ part,
                                  const float* __restrict__ xv, const float* __restrict__ xa,
                                  const float* __restrict__ tcp,
                                  const float* __restrict__ mv, const float* __restrict__ ma,
                                  float* __restrict__ o1, float* __restrict__ o2)
{
    int i = blockIdx.x * 256 + threadIdx.x;
    float s = part[i] + part[i + N_BSD] + part[i + 2 * N_BSD] + part[i + 3 * N_BSD];
    float j = sigm(s);
    float m = (*tcp) * j * xv[i] + (1.0f - j) * xa[i];
    o1[i] = m * mv[i];
    o2[i] = m * ma[i];
}

// ---------------- attention: q/k from N-fused buffers (row stride 512) -----------------
__global__ void __launch_bounds__(256) attn_kernel(
    const float* __restrict__ xv, const float* __restrict__ xa,
    const float* __restrict__ qkv_v, const float* __restrict__ qkv_a,
    float* __restrict__ cat1, float* __restrict__ cat2)
{
    __shared__ float s_x[2][3][256];
    __shared__ float s_q[2][3][256];
    __shared__ float s_k[2][3][256];
    __shared__ float s_sc[4][3][3];
    const int tid = threadIdx.x;
    const size_t base = (size_t)blockIdx.x * 768;
    const size_t base2 = (size_t)blockIdx.x * 1536;
    const size_t qbase = (size_t)blockIdx.x * 3 * 512;

    float* fx = &s_x[0][0][0];
    float* fq = &s_q[0][0][0];
    float* fk = &s_k[0][0][0];
    for (int idx = tid; idx < 768; idx += 256) {
        int s3 = idx >> 8, d = idx & 255;
        size_t qoff = qbase + (size_t)s3 * 512 + d;
        fx[idx] = xv[base + idx]; fx[768 + idx] = xa[base + idx];
        fq[idx] = qkv_v[qoff];        fq[768 + idx] = qkv_a[qoff];
        fk[idx] = qkv_v[qoff + 256];  fk[768 + idx] = qkv_a[qoff + 256];
    }
    __syncthreads();

    const int w = tid >> 5, lane = tid & 31;
    for (int task = w; task < 36; task += 8) {
        int type = task / 9, rem = task % 9, s3 = rem / 3, t3 = rem % 3;
        int qsel = type >> 1;
        int ksel = (type == 0 || type == 3) ? 1 : 0;
        float sum = 0.0f;
        for (int d = lane; d < 256; d += 32) sum += s_q[qsel][s3][d] * s_k[ksel][t3][d];
#pragma unroll
        for (int off = 16; off; off >>= 1) sum += __shfl_down_sync(0xffffffffu, sum, off);
        if (lane == 0) s_sc[type][s3][t3] = sum;
    }
    __syncthreads();

    if (tid < 12) {
        int type = tid / 3, s3 = tid % 3;
        float a = s_sc[type][s3][0], b = s_sc[type][s3][1], c = s_sc[type][s3][2];
        float m = fmaxf(a, fmaxf(b, c));
        float ea = expf(a - m), eb = expf(b - m), ec = expf(c - m);
        float inv = 0.0625f / (ea + eb + ec);
        s_sc[type][s3][0] = ea * inv; s_sc[type][s3][1] = eb * inv; s_sc[type][s3][2] = ec * inv;
    }
    __syncthreads();

    for (int idx = tid; idx < 3072; idx += 256) {
        int type = idx / 768, rem = idx % 768;
        int s3 = rem >> 8, d = rem & 255;
        int xsel = (type == 0 || type == 3) ? 1 : 0;
        float v = s_sc[type][s3][0] * s_x[xsel][0][d]
                + s_sc[type][s3][1] * s_x[xsel][1][d]
                + s_sc[type][s3][2] * s_x[xsel][2][d];
        float* dst = (type < 2) ? cat1 : cat2;
        dst[base2 + (size_t)s3 * 512 + ((type & 1) ? 256 : 0) + d] = v;
    }
}

// ---------------- classifier ----------------
__global__ void __launch_bounds__(256) cls_kernel(
    const float* __restrict__ F, const float* __restrict__ W1,
    const float* __restrict__ W2, float* __restrict__ P)
{
    __shared__ float s_f[8][128];
    __shared__ float s_w1[32][129];
    __shared__ float s_w2[320];
    __shared__ float s_h[8][32];
    const int tid = threadIdx.x;
    const int r0 = blockIdx.x * 8;
    for (int idx = tid; idx < 1024; idx += 256) s_f[idx >> 7][idx & 127] = F[(size_t)r0 * 128 + idx];
    for (int idx = tid; idx < 4096; idx += 256) s_w1[idx >> 7][idx & 127] = W1[idx];
    for (int idx = tid; idx < 320; idx += 256) s_w2[idx] = W2[idx];
    __syncthreads();
    const int w = tid >> 5, lane = tid & 31;
    float h = 0.0f;
#pragma unroll 8
    for (int d = 0; d < 128; d++) h = fmaf(s_f[w][d], s_w1[lane][d], h);
    s_h[w][lane] = fmaxf(h, 0.0f);
    __syncwarp();
    if (lane < 10) {
        float p = 0.0f;
#pragma unroll
        for (int k = 0; k < 32; k++) p = fmaf(s_h[w][k], s_w2[lane * 32 + k], p);
        P[(size_t)(r0 + w) * 10 + lane] = p;
    }
}

// ---------------- host ----------------
static void launch_gemm_f32(const float* A, const float* W, const float* b, float* C,
                            int M, int N, int K, int flags)
{
    dim3 grid(N / BN, M / BM);
    gemm_kernel<<<grid, 256>>>(A, W, b, C, M, N, K, flags);
}

static void launch_mma(const float* A, const float* W, const float* b, float* C,
                       int M, int N, int K, int flags,
                       const float* W2 = nullptr, int Kx = -1, const float* b2 = nullptr,
                       const float* E = nullptr, int eld = 0, int eoff = 0)
{
    if (Kx < 0) { Kx = K; W2 = W; }
    if (!b2) b2 = b;
    if (!E) E = A;
    dim3 grid(N / 64, M / 64);
    mma_gemm_kernel<<<grid, 128>>>(A, W, W2, b, b2, C, M, N, K, Kx, flags, E, eld, eoff);
}

extern "C" void kernel_launch(void* const* d_in, const int* in_sizes, int n_in,
                              void* d_out, int out_size)
{
    const float* img    = (const float*)d_in[0];
    const float* audio  = (const float*)d_in[1];
    const float* vis_W  = (const float*)d_in[2];
    const float* vis_b  = (const float*)d_in[3];
    const float* aud_W  = (const float*)d_in[4];
    const float* aud_b  = (const float*)d_in[5];
    const float* msv_W  = (const float*)d_in[6];
    const float* msv_b  = (const float*)d_in[7];
    const float* msa_W  = (const float*)d_in[8];
    const float* msa_b  = (const float*)d_in[9];
    const float* mmfaW  = (const float*)d_in[10];
    const float* mmfaB  = (const float*)d_in[11];
    const float* bilW   = (const float*)d_in[12];
    const float* t_c    = (const float*)d_in[13];
    const float* out_W1 = (const float*)d_in[14];
    const float* out_b1 = (const float*)d_in[15];
    const float* out_W2 = (const float*)d_in[16];
    const float* out_b2 = (const float*)d_in[17];
    const float* clsvW1 = (const float*)d_in[18];
    const float* clsvW2 = (const float*)d_in[19];
    const float* clsaW1 = (const float*)d_in[20];
    const float* clsaW2 = (const float*)d_in[21];

    float* S = nullptr;
    cudaGetSymbolAddress((void**)&S, g_scratch);
    float* p_bf = nullptr;
    cudaGetSymbolAddress((void**)&p_bf, g_bias_fused);
    __half* p_Wh = nullptr;
    cudaGetSymbolAddress((void**)&p_Wh, g_Wh);

    float* p_vis  = S;
    float* p_aud  = p_vis + N_BE;
    float* p_vms  = p_aud + N_BE;
    float* p_ams  = p_vms + N_BSD;
    float* p_qkv  = p_ams + N_BSD;        // [3072][512] (qv | kv)
    float* p_qka  = p_qkv + 2 * N_BSD;    // [3072][512] (qa | ka)
    float* p_cat1 = p_qka + 2 * N_BSD;    // [3072][512]
    float* p_cat2 = p_cat1 + 2 * N_BSD;   // [3072][512]
    float* p_cva  = p_cat2 + 2 * N_BSD;
    float* p_cav  = p_cva + N_BSD;
    float* p_bp   = p_cav + N_BSD;        // 4 x [3072][256]
    float* p_xv   = p_bp  + 4 * N_BSD;
    float* p_xa   = p_xv  + N_BSD;
    float* p_ov   = p_xa  + N_BSD;        // p_ov/p_oa contiguous -> [2048][768]
    float* p_oa   = p_ov  + N_BSD;
    float* p_h    = p_oa  + N_BSD;        // [2048][512]

    const int nBlk = (int)(N_BSD / 256);

    cudaFuncSetAttribute(bilinear2_kernel,
                         cudaFuncAttributeMaxDynamicSharedMemorySize, BIL2_SMEM_BYTES);

    // one-time prep (re-runs each launch; deterministic)
    fuse_bias_kernel<<<1, 256>>>(mmfaB, p_bf);
    wconv_kernel<<<16384, 256>>>(bilW, p_Wh);
    float* p_b45 = p_bf;
    float* p_b67 = p_bf + 256;

    auto run_mmfa = [&](const float* xv, const float* xa,
                        const float* mv, const float* ma, float* o1, float* o2) {
        // q_v|k_v from xv (W0,W2), q_a|k_a from xa (W1,W3) -- N-split fused GEMMs
        launch_mma(xv, mmfaW + 0 * 65536, mmfaB + 0 * 256, p_qkv, M3, 512, Dd, 8,
                   mmfaW + 2 * 65536, 256, mmfaB + 2 * 256);
        launch_mma(xa, mmfaW + 1 * 65536, mmfaB + 1 * 256, p_qka, M3, 512, Dd, 8,
                   mmfaW + 3 * 65536, 256, mmfaB + 3 * 256);
        attn_kernel<<<Bn, 256>>>(xv, xa, p_qkv, p_qka, p_cat1, p_cat2);
        // c_va = sigm((lin4(ava)+lin5(av)+b4+b5) * av) : K=512 K-split GEMM + epilogue
        launch_mma(p_cat1, mmfaW + 4 * 65536, p_b45, p_cva, M3, Dd, 512, 4,
                   mmfaW + 5 * 65536, 256, nullptr, p_cat1, 512, 256);
        launch_mma(p_cat2, mmfaW + 6 * 65536, p_b67, p_cav, M3, Dd, 512, 4,
                   mmfaW + 7 * 65536, 256, nullptr, p_cat2, 512, 256);
        dim3 bg(48, 2, 4);
        bilinear2_kernel<<<bg, 256, BIL2_SMEM_BYTES>>>(p_cva, p_cav, p_Wh, p_bp);
        bil_finish_kernel<<<nBlk, 256>>>(p_bp, xv, xa, t_c, mv, ma, o1, o2);
    };

    // encoders + multi-scale: fp32 SIMT for precision (root of the error chain)
    launch_gemm_f32(img,   vis_W, vis_b, p_vis, Bn, 1024, 4096, 1);
    launch_gemm_f32(audio, aud_W, aud_b, p_aud, Bn, 1024, 1024, 1);
    launch_gemm_f32(p_vis, msv_W, msv_b, p_vms, Bn, SD, 1024, 1);
    launch_gemm_f32(p_aud, msa_W, msa_b, p_ams, Bn, SD, 1024, 1);

    // MMfa 1: outputs xv2 = M1*vms, xa2 = M1*ams directly
    run_mmfa(p_vms, p_ams, p_vms, p_ams, p_xv, p_xa);
    // MMfa 2: outputs ov = M2*vms, oa = M2*ams directly
    run_mmfa(p_xv, p_xa, p_vms, p_ams, p_ov, p_oa);

    float* out = (float*)d_out;
    float* fv = out;
    float* fa = out + (size_t)Bn * LAT;
    float* pv = fa + (size_t)Bn * LAT;
    float* pa = pv + (size_t)Bn * 10;

    // out_layer M-batched over (ov||oa) -> (fv||fa)
    launch_mma(p_ov, out_W1, out_b1, p_h, 2 * Bn, OUT1, SD, 1);
    launch_mma(p_h,  out_W2, out_b2, fv,  2 * Bn, LAT, OUT1, 0);

    cls_kernel<<<Bn / 8, 256>>>(fv, clsvW1, clsvW2, pv);
    cls_kernel<<<Bn / 8, 256>>>(fa, clsaW1, clsaW2, pa);
}

// round 6
// speedup vs baseline: 1.0738x; 1.0738x over previous
#include <cuda_runtime.h>
#include <cuda_fp16.h>
#include <math.h>
#include <stdint.h>

// ---------------- problem constants ----------------
static constexpr int Bn   = 1024;
static constexpr int M3   = 3072;   // B*S
static constexpr int Dd   = 256;
static constexpr int SD   = 768;
static constexpr int OUT1 = 512;
static constexpr int LAT  = 128;

static constexpr size_t N_BE  = (size_t)Bn * 1024;
static constexpr size_t N_BSD = (size_t)M3 * Dd;     // 786432

__device__ float g_scratch[2 * N_BE + 22 * N_BSD + (size_t)Bn * OUT1];
__device__ float g_bias_fused[512];            // [0:256)=b4+b5, [256:512)=b6+b7
__device__ __half g_Wh[16777216];              // bil_W in fp16 (32MB)

__device__ __forceinline__ float sigm(float x) { return 1.0f / (1.0f + expf(-x)); }

__device__ __forceinline__ unsigned tf32r(float x) {
    unsigned r;
    asm("cvt.rna.tf32.f32 %0, %1;" : "=r"(r) : "f"(x));
    return r;
}

__device__ __forceinline__ void mma_tf32(float& c0, float& c1, float& c2, float& c3,
                                         unsigned a0, unsigned a1, unsigned a2, unsigned a3,
                                         unsigned b0, unsigned b1) {
    asm("mma.sync.aligned.m16n8k8.row.col.f32.tf32.tf32.f32 "
        "{%0,%1,%2,%3}, {%4,%5,%6,%7}, {%8,%9}, {%0,%1,%2,%3};"
        : "+f"(c0), "+f"(c1), "+f"(c2), "+f"(c3)
        : "r"(a0), "r"(a1), "r"(a2), "r"(a3), "r"(b0), "r"(b1));
}

__device__ __forceinline__ void mma_f16(float& c0, float& c1, float& c2, float& c3,
                                        unsigned a0, unsigned a1, unsigned a2, unsigned a3,
                                        unsigned b0, unsigned b1) {
    asm("mma.sync.aligned.m16n8k16.row.col.f32.f16.f16.f32 "
        "{%0,%1,%2,%3}, {%4,%5,%6,%7}, {%8,%9}, {%0,%1,%2,%3};"
        : "+f"(c0), "+f"(c1), "+f"(c2), "+f"(c3)
        : "r"(a0), "r"(a1), "r"(a2), "r"(a3), "r"(b0), "r"(b1));
}

// ---------------- helpers ----------------
__global__ void fuse_bias_kernel(const float* __restrict__ b, float* __restrict__ o)
{
    int i = threadIdx.x;
    o[i]       = b[4 * 256 + i] + b[5 * 256 + i];
    o[256 + i] = b[6 * 256 + i] + b[7 * 256 + i];
}

__global__ void wconv_kernel(const float* __restrict__ W, __half* __restrict__ Wh)
{
    size_t i = ((size_t)blockIdx.x * 256 + threadIdx.x) * 4;
    float4 v = *(const float4*)(W + i);
    *(__half2*)(Wh + i)     = __floats2half2_rn(v.x, v.y);
    *(__half2*)(Wh + i + 2) = __floats2half2_rn(v.z, v.w);
}

// ---------------- fp32 SIMT GEMM v2: 128x64 tile, 256 threads, 32 acc/thread ----------
__global__ void __launch_bounds__(256) gemm_kernel(
    const float* __restrict__ A, const float* __restrict__ W,
    const float* __restrict__ bias, float* __restrict__ C,
    int M, int N, int K, int flags)
{
    __shared__ __align__(16) float As[16][132];
    __shared__ __align__(16) float Ws[16][68];
    const int tid = threadIdx.x;
    const int tx = tid & 15, ty = tid >> 4;     // tx: n-quad (4 cols), ty: m-oct (8 rows)
    const int m0 = blockIdx.y * 128, n0 = blockIdx.x * 64;
    const int lrow = tid >> 2, lk = (tid & 3) << 2;

    const float* Ag0 = A + (size_t)(m0 + lrow) * K + lk;
    const float* Ag1 = A + (size_t)(m0 + lrow + 64) * K + lk;
    const float* Wg  = W + (size_t)(n0 + lrow) * K + lk;

    float acc[8][4] = {};
    for (int kt = 0; kt < K; kt += 16) {
        float4 a0 = *(const float4*)(Ag0 + kt);
        float4 a1 = *(const float4*)(Ag1 + kt);
        float4 w0 = *(const float4*)(Wg + kt);
        As[lk + 0][lrow] = a0.x; As[lk + 1][lrow] = a0.y;
        As[lk + 2][lrow] = a0.z; As[lk + 3][lrow] = a0.w;
        As[lk + 0][lrow + 64] = a1.x; As[lk + 1][lrow + 64] = a1.y;
        As[lk + 2][lrow + 64] = a1.z; As[lk + 3][lrow + 64] = a1.w;
        Ws[lk + 0][lrow] = w0.x; Ws[lk + 1][lrow] = w0.y;
        Ws[lk + 2][lrow] = w0.z; Ws[lk + 3][lrow] = w0.w;
        __syncthreads();
#pragma unroll
        for (int k = 0; k < 16; k++) {
            float ar[8];
            *(float4*)&ar[0] = *(const float4*)&As[k][ty * 8];
            *(float4*)&ar[4] = *(const float4*)&As[k][ty * 8 + 4];
            float4 b = *(const float4*)&Ws[k][tx * 4];
#pragma unroll
            for (int i = 0; i < 8; i++) {
                acc[i][0] = fmaf(ar[i], b.x, acc[i][0]);
                acc[i][1] = fmaf(ar[i], b.y, acc[i][1]);
                acc[i][2] = fmaf(ar[i], b.z, acc[i][2]);
                acc[i][3] = fmaf(ar[i], b.w, acc[i][3]);
            }
        }
        __syncthreads();
    }
#pragma unroll
    for (int i = 0; i < 8; i++) {
        int row = m0 + ty * 8 + i;
#pragma unroll
        for (int j = 0; j < 4; j++) {
            int col = n0 + tx * 4 + j;
            float v = acc[i][j] + bias[col];
            if (flags & 1) v = fmaxf(v, 0.0f);
            C[(size_t)row * N + col] = v;
        }
    }
}

// ---------------- tf32 tensor GEMM: K-split or N-split weights + fused epilogue -------
// flags: bit0 relu ; bit2 sigmul: out = sigm(v * E[row*eld + eoff + col]) ; bit3 N-split
__global__ void __launch_bounds__(128) mma_gemm_kernel(
    const float* __restrict__ A, const float* __restrict__ W, const float* __restrict__ W2,
    const float* __restrict__ bias, const float* __restrict__ bias2, float* __restrict__ C,
    int M, int N, int K, int Kx, int flags,
    const float* __restrict__ E, int eld, int eoff)
{
    __shared__ float As[16][72];
    __shared__ float Ws[16][72];
    const int tid = threadIdx.x;
    const int lane = tid & 31, wid = tid >> 5;
    const int wm = wid >> 1, wn = wid & 1;
    const int m0 = blockIdx.y * 64, n0 = blockIdx.x * 64;
    const int c4 = lane & 3, lr = lane >> 2;
    const int Kb = K - Kx;
    const bool nsplit = (flags & 8) != 0;

    float c[2][4][4];
#pragma unroll
    for (int mt = 0; mt < 2; mt++)
#pragma unroll
        for (int nt = 0; nt < 4; nt++)
#pragma unroll
            for (int e = 0; e < 4; e++) c[mt][nt][e] = 0.0f;

    const int lrow = tid >> 2, lsq = tid & 3;
    float4 pa[2], pw[2];
    {
        int k = lsq * 4;
#pragma unroll
        for (int u = 0; u < 2; u++) {
            int row = lrow + u * 32;
            pa[u] = *(const float4*)(A + (size_t)(m0 + row) * K + k);
            const float* ws;
            if (nsplit) {
                int n = n0 + row;
                ws = (n < Kx) ? (W + (size_t)n * K + k) : (W2 + (size_t)(n - Kx) * K + k);
            } else {
                ws = (k < Kx) ? (W + (size_t)(n0 + row) * Kx + k)
                              : (W2 + (size_t)(n0 + row) * Kb + (k - Kx));
            }
            pw[u] = *(const float4*)ws;
        }
    }

    const int ktiles = K >> 4;
    for (int kt = 0; kt < ktiles; kt++) {
#pragma unroll
        for (int u = 0; u < 2; u++) {
            int row = lrow + u * 32;
            As[lsq * 4 + 0][row] = __uint_as_float(tf32r(pa[u].x));
            As[lsq * 4 + 1][row] = __uint_as_float(tf32r(pa[u].y));
            As[lsq * 4 + 2][row] = __uint_as_float(tf32r(pa[u].z));
            As[lsq * 4 + 3][row] = __uint_as_float(tf32r(pa[u].w));
            Ws[lsq * 4 + 0][row] = __uint_as_float(tf32r(pw[u].x));
            Ws[lsq * 4 + 1][row] = __uint_as_float(tf32r(pw[u].y));
            Ws[lsq * 4 + 2][row] = __uint_as_float(tf32r(pw[u].z));
            Ws[lsq * 4 + 3][row] = __uint_as_float(tf32r(pw[u].w));
        }
        __syncthreads();
        if (kt + 1 < ktiles) {
            int k = (kt + 1) * 16 + lsq * 4;
#pragma unroll
            for (int u = 0; u < 2; u++) {
                int row = lrow + u * 32;
                pa[u] = *(const float4*)(A + (size_t)(m0 + row) * K + k);
                const float* ws;
                if (nsplit) {
                    int n = n0 + row;
                    ws = (n < Kx) ? (W + (size_t)n * K + k) : (W2 + (size_t)(n - Kx) * K + k);
                } else {
                    ws = (k < Kx) ? (W + (size_t)(n0 + row) * Kx + k)
                                  : (W2 + (size_t)(n0 + row) * Kb + (k - Kx));
                }
                pw[u] = *(const float4*)ws;
            }
        }
#pragma unroll
        for (int kk = 0; kk < 16; kk += 8) {
            unsigned a[2][4];
#pragma unroll
            for (int mt = 0; mt < 2; mt++) {
                int rb = wm * 32 + mt * 16 + lr;
                a[mt][0] = __float_as_uint(As[kk + c4][rb]);
                a[mt][1] = __float_as_uint(As[kk + c4][rb + 8]);
                a[mt][2] = __float_as_uint(As[kk + c4 + 4][rb]);
                a[mt][3] = __float_as_uint(As[kk + c4 + 4][rb + 8]);
            }
#pragma unroll
            for (int nt = 0; nt < 4; nt++) {
                int nb = wn * 32 + nt * 8 + lr;
                unsigned b0 = __float_as_uint(Ws[kk + c4][nb]);
                unsigned b1 = __float_as_uint(Ws[kk + c4 + 4][nb]);
#pragma unroll
                for (int mt = 0; mt < 2; mt++)
                    mma_tf32(c[mt][nt][0], c[mt][nt][1], c[mt][nt][2], c[mt][nt][3],
                             a[mt][0], a[mt][1], a[mt][2], a[mt][3], b0, b1);
            }
        }
        __syncthreads();
    }

#pragma unroll
    for (int mt = 0; mt < 2; mt++) {
#pragma unroll
        for (int nt = 0; nt < 4; nt++) {
            int row = m0 + wm * 32 + mt * 16 + lr;
            int col = n0 + wn * 32 + nt * 8 + c4 * 2;
#pragma unroll
            for (int e = 0; e < 4; e++) {
                int rr = row + (e >> 1) * 8;
                int cc = col + (e & 1);
                float bv = nsplit ? ((cc < Kx) ? bias[cc] : bias2[cc - Kx]) : bias[cc];
                float v = c[mt][nt][e] + bv;
                if (flags & 1) v = fmaxf(v, 0.0f);
                if (flags & 4) v = sigm(v * E[(size_t)rr * eld + eoff + cc]);
                C[(size_t)rr * N + cc] = v;
            }
        }
    }
}

// ---------------- fp16 bilinear v3: r-tile 128, o-tile 64, hmul2 E, cp.async W --------
// grid (24, 4, 4): r-block 128, o-block 64, i-range 64. 256 threads = 8 warps (4m x 2n).
// smem: s_cav [128][264] fp16 (67.6KB) + s_W [2][64][72] fp16 (18.4KB) = 86KB
static constexpr int BIL3_SMEM_BYTES = (128 * 264 + 2 * 64 * 72) * 2;

__global__ void __launch_bounds__(256) bilinear3_kernel(
    const float* __restrict__ cva, const float* __restrict__ cav,
    const __half* __restrict__ Wh, float* __restrict__ part)
{
    extern __shared__ __half sh[];
    __half* s_cav = sh;                // [128][264]
    __half* s_W   = sh + 128 * 264;    // [2][64][72]

    const int tid = threadIdx.x;
    const int lane = tid & 31, wid = tid >> 5;
    const int wm = wid & 3, wn = wid >> 2;   // 4m x 2n
    const int g = lane >> 2, q = lane & 3;
    const int r0 = blockIdx.x * 128, o0 = blockIdx.y * 64;
    const int iBase = blockIdx.z * 64;

    // load cav rows [r0, r0+128) -> fp16 smem
    for (int f = tid; f < 8192; f += 256) {
        int row = f >> 6, q4 = f & 63;
        float4 w = *(const float4*)(cav + (size_t)(r0 + row) * 256 + q4 * 4);
        __half* d = s_cav + row * 264 + q4 * 4;
        *(__half2*)(d)     = __floats2half2_rn(w.x, w.y);
        *(__half2*)(d + 2) = __floats2half2_rn(w.z, w.w);
    }

    float c[2][4][4];
#pragma unroll
    for (int mt = 0; mt < 2; mt++)
#pragma unroll
        for (int nt = 0; nt < 4; nt++)
#pragma unroll
            for (int e = 0; e < 4; e++) c[mt][nt][e] = 0.0f;

    // cp.async W tile: 64 o x 64 j halves = 8KB = 512 x 16B chunks, 2 per thread
    auto issue_tile = [&](int it) {
        int i = iBase + (it >> 2), h = it & 3;
        __half* dst0 = s_W + (it & 1) * 64 * 72;
#pragma unroll
        for (int u = 0; u < 2; u++) {
            int cidx = tid + 256 * u;          // 0..511
            int o = cidx >> 3, ch = cidx & 7;
            const __half* src = Wh + (size_t)(o0 + o) * 65536 + (size_t)i * 256 + h * 64 + ch * 8;
            unsigned sa = (unsigned)__cvta_generic_to_shared(dst0 + o * 72 + ch * 8);
            asm volatile("cp.async.cg.shared.global [%0], [%1], 16;" :: "r"(sa), "l"(src));
        }
        asm volatile("cp.async.commit_group;");
    };

    issue_tile(0);
    __syncthreads();   // s_cav ready

    const int rbase = wm * 32 + g;
    const float* cvaB = cva + (size_t)(r0 + rbase) * 256;

    for (int it = 0; it < 256; it++) {
        if (it + 1 < 256) {
            issue_tile(it + 1);
            asm volatile("cp.async.wait_group 1;");
        } else {
            asm volatile("cp.async.wait_group 0;");
        }
        __syncthreads();   // tile(it) visible

        const __half* wbuf = s_W + (it & 1) * 64 * 72;
        const int ig = iBase + (it >> 2);
        const int h = it & 3;
        // cva scalars: fp32 gmem loads (L1 broadcast), single rounding to fp16
        __half2 s0 = __half2half2(__float2half_rn(cvaB[ig]));
        __half2 s1 = __half2half2(__float2half_rn(cvaB[8 * 256 + ig]));
        __half2 s2 = __half2half2(__float2half_rn(cvaB[16 * 256 + ig]));
        __half2 s3 = __half2half2(__float2half_rn(cvaB[24 * 256 + ig]));

#pragma unroll
        for (int jc = 0; jc < 4; jc++) {
            const int jlo = h * 64 + jc * 16 + 2 * q;
            const int jhi = jlo + 8;
            __half2 a[2][4];
            a[0][0] = __hmul2(*(__half2*)&s_cav[(rbase)      * 264 + jlo], s0);
            a[0][1] = __hmul2(*(__half2*)&s_cav[(rbase + 8)  * 264 + jlo], s1);
            a[0][2] = __hmul2(*(__half2*)&s_cav[(rbase)      * 264 + jhi], s0);
            a[0][3] = __hmul2(*(__half2*)&s_cav[(rbase + 8)  * 264 + jhi], s1);
            a[1][0] = __hmul2(*(__half2*)&s_cav[(rbase + 16) * 264 + jlo], s2);
            a[1][1] = __hmul2(*(__half2*)&s_cav[(rbase + 24) * 264 + jlo], s3);
            a[1][2] = __hmul2(*(__half2*)&s_cav[(rbase + 16) * 264 + jhi], s2);
            a[1][3] = __hmul2(*(__half2*)&s_cav[(rbase + 24) * 264 + jhi], s3);
            const int kloc = jc * 16;
#pragma unroll
            for (int nt = 0; nt < 4; nt++) {
                int oc = wn * 32 + nt * 8 + g;
                unsigned b0 = *(const unsigned*)&wbuf[oc * 72 + kloc + 2 * q];
                unsigned b1 = *(const unsigned*)&wbuf[oc * 72 + kloc + 2 * q + 8];
#pragma unroll
                for (int mt = 0; mt < 2; mt++)
                    mma_f16(c[mt][nt][0], c[mt][nt][1], c[mt][nt][2], c[mt][nt][3],
                            *(unsigned*)&a[mt][0], *(unsigned*)&a[mt][1],
                            *(unsigned*)&a[mt][2], *(unsigned*)&a[mt][3], b0, b1);
            }
        }
        __syncthreads();   // done reading buffer before refill
    }

    float* P = part + (size_t)blockIdx.z * N_BSD;
#pragma unroll
    for (int mt = 0; mt < 2; mt++) {
#pragma unroll
        for (int nt = 0; nt < 4; nt++) {
            int row = r0 + wm * 32 + mt * 16 + g;
            int col = o0 + wn * 32 + nt * 8 + q * 2;
            float* d0 = P + (size_t)row * 256 + col;
            float* d1 = P + (size_t)(row + 8) * 256 + col;
            d0[0] = c[mt][nt][0]; d0[1] = c[mt][nt][1];
            d1[0] = c[mt][nt][2]; d1[1] = c[mt][nt][3];
        }
    }
}

// finish: j = sigm(sum partials); m = tc*j*xv + (1-j)*xa; o1 = m*mv; o2 = m*ma
__global__ void bil_finish_kernel(const float* __restrict__ part,
                                  const float* __restrict__ xv, const float* __restrict__ xa,
                                  const float* __restrict__ tcp,
                                  const float* __restrict__ mv, const float* __restrict__ ma,
                                  float* __restrict__ o1, float* __restrict__ o2)
{
    int i = blockIdx.x * 256 + threadIdx.x;
    float s = part[i] + part[i + N_BSD] + part[i + 2 * N_BSD] + part[i + 3 * N_BSD];
    float j = sigm(s);
    float m = (*tcp) * j * xv[i] + (1.0f - j) * xa[i];
    o1[i] = m * mv[i];
    o2[i] = m * ma[i];
}

// ---------------- attention ----------------
__global__ void __launch_bounds__(256) attn_kernel(
    const float* __restrict__ xv, const float* __restrict__ xa,
    const float* __restrict__ qkv_v, const float* __restrict__ qkv_a,
    float* __restrict__ cat1, float* __restrict__ cat2)
{
    __shared__ float s_x[2][3][256];
    __shared__ float s_q[2][3][256];
    __shared__ float s_k[2][3][256];
    __shared__ float s_sc[4][3][3];
    const int tid = threadIdx.x;
    const size_t base = (size_t)blockIdx.x * 768;
    const size_t base2 = (size_t)blockIdx.x * 1536;
    const size_t qbase = (size_t)blockIdx.x * 3 * 512;

    float* fx = &s_x[0][0][0];
    float* fq = &s_q[0][0][0];
    float* fk = &s_k[0][0][0];
    for (int idx = tid; idx < 768; idx += 256) {
        int s3 = idx >> 8, d = idx & 255;
        size_t qoff = qbase + (size_t)s3 * 512 + d;
        fx[idx] = xv[base + idx]; fx[768 + idx] = xa[base + idx];
        fq[idx] = qkv_v[qoff];        fq[768 + idx] = qkv_a[qoff];
        fk[idx] = qkv_v[qoff + 256];  fk[768 + idx] = qkv_a[qoff + 256];
    }
    __syncthreads();

    const int w = tid >> 5, lane = tid & 31;
    for (int task = w; task < 36; task += 8) {
        int type = task / 9, rem = task % 9, s3 = rem / 3, t3 = rem % 3;
        int qsel = type >> 1;
        int ksel = (type == 0 || type == 3) ? 1 : 0;
        float sum = 0.0f;
        for (int d = lane; d < 256; d += 32) sum += s_q[qsel][s3][d] * s_k[ksel][t3][d];
#pragma unroll
        for (int off = 16; off; off >>= 1) sum += __shfl_down_sync(0xffffffffu, sum, off);
        if (lane == 0) s_sc[type][s3][t3] = sum;
    }
    __syncthreads();

    if (tid < 12) {
        int type = tid / 3, s3 = tid % 3;
        float a = s_sc[type][s3][0], b = s_sc[type][s3][1], c = s_sc[type][s3][2];
        float m = fmaxf(a, fmaxf(b, c));
        float ea = expf(a - m), eb = expf(b - m), ec = expf(c - m);
        float inv = 0.0625f / (ea + eb + ec);
        s_sc[type][s3][0] = ea * inv; s_sc[type][s3][1] = eb * inv; s_sc[type][s3][2] = ec * inv;
    }
    __syncthreads();

    for (int idx = tid; idx < 3072; idx += 256) {
        int type = idx / 768, rem = idx % 768;
        int s3 = rem >> 8, d = rem & 255;
        int xsel = (type == 0 || type == 3) ? 1 : 0;
        float v = s_sc[type][s3][0] * s_x[xsel][0][d]
                + s_sc[type][s3][1] * s_x[xsel][1][d]
                + s_sc[type][s3][2] * s_x[xsel][2][d];
        float* dst = (type < 2) ? cat1 : cat2;
        dst[base2 + (size_t)s3 * 512 + ((type & 1) ? 256 : 0) + d] = v;
    }
}

// ---------------- classifier ----------------
__global__ void __launch_bounds__(256) cls_kernel(
    const float* __restrict__ F, const float* __restrict__ W1,
    const float* __restrict__ W2, float* __restrict__ P)
{
    __shared__ float s_f[8][128];
    __shared__ float s_w1[32][129];
    __shared__ float s_w2[320];
    __shared__ float s_h[8][32];
    const int tid = threadIdx.x;
    const int r0 = blockIdx.x * 8;
    for (int idx = tid; idx < 1024; idx += 256) s_f[idx >> 7][idx & 127] = F[(size_t)r0 * 128 + idx];
    for (int idx = tid; idx < 4096; idx += 256) s_w1[idx >> 7][idx & 127] = W1[idx];
    for (int idx = tid; idx < 320; idx += 256) s_w2[idx] = W2[idx];
    __syncthreads();
    const int w = tid >> 5, lane = tid & 31;
    float h = 0.0f;
#pragma unroll 8
    for (int d = 0; d < 128; d++) h = fmaf(s_f[w][d], s_w1[lane][d], h);
    s_h[w][lane] = fmaxf(h, 0.0f);
    __syncwarp();
    if (lane < 10) {
        float p = 0.0f;
#pragma unroll
        for (int k = 0; k < 32; k++) p = fmaf(s_h[w][k], s_w2[lane * 32 + k], p);
        P[(size_t)(r0 + w) * 10 + lane] = p;
    }
}

// ---------------- host ----------------
static void launch_gemm_f32(const float* A, const float* W, const float* b, float* C,
                            int M, int N, int K, int flags)
{
    dim3 grid(N / 64, M / 128);
    gemm_kernel<<<grid, 256>>>(A, W, b, C, M, N, K, flags);
}

static void launch_mma(const float* A, const float* W, const float* b, float* C,
                       int M, int N, int K, int flags,
                       const float* W2 = nullptr, int Kx = -1, const float* b2 = nullptr,
                       const float* E = nullptr, int eld = 0, int eoff = 0)
{
    if (Kx < 0) { Kx = K; W2 = W; }
    if (!b2) b2 = b;
    if (!E) E = A;
    dim3 grid(N / 64, M / 64);
    mma_gemm_kernel<<<grid, 128>>>(A, W, W2, b, b2, C, M, N, K, Kx, flags, E, eld, eoff);
}

extern "C" void kernel_launch(void* const* d_in, const int* in_sizes, int n_in,
                              void* d_out, int out_size)
{
    const float* img    = (const float*)d_in[0];
    const float* audio  = (const float*)d_in[1];
    const float* vis_W  = (const float*)d_in[2];
    const float* vis_b  = (const float*)d_in[3];
    const float* aud_W  = (const float*)d_in[4];
    const float* aud_b  = (const float*)d_in[5];
    const float* msv_W  = (const float*)d_in[6];
    const float* msv_b  = (const float*)d_in[7];
    const float* msa_W  = (const float*)d_in[8];
    const float* msa_b  = (const float*)d_in[9];
    const float* mmfaW  = (const float*)d_in[10];
    const float* mmfaB  = (const float*)d_in[11];
    const float* bilW   = (const float*)d_in[12];
    const float* t_c    = (const float*)d_in[13];
    const float* out_W1 = (const float*)d_in[14];
    const float* out_b1 = (const float*)d_in[15];
    const float* out_W2 = (const float*)d_in[16];
    const float* out_b2 = (const float*)d_in[17];
    const float* clsvW1 = (const float*)d_in[18];
    const float* clsvW2 = (const float*)d_in[19];
    const float* clsaW1 = (const float*)d_in[20];
    const float* clsaW2 = (const float*)d_in[21];

    float* S = nullptr;
    cudaGetSymbolAddress((void**)&S, g_scratch);
    float* p_bf = nullptr;
    cudaGetSymbolAddress((void**)&p_bf, g_bias_fused);
    __half* p_Wh = nullptr;
    cudaGetSymbolAddress((void**)&p_Wh, g_Wh);

    float* p_vis  = S;
    float* p_aud  = p_vis + N_BE;
    float* p_vms  = p_aud + N_BE;
    float* p_ams  = p_vms + N_BSD;
    float* p_qkv  = p_ams + N_BSD;        // [3072][512] (qv | kv)
    float* p_qka  = p_qkv + 2 * N_BSD;    // [3072][512] (qa | ka)
    float* p_cat1 = p_qka + 2 * N_BSD;    // [3072][512]
    float* p_cat2 = p_cat1 + 2 * N_BSD;   // [3072][512]
    float* p_cva  = p_cat2 + 2 * N_BSD;
    float* p_cav  = p_cva + N_BSD;
    float* p_bp   = p_cav + N_BSD;        // 4 x [3072][256]
    float* p_xv   = p_bp  + 4 * N_BSD;
    float* p_xa   = p_xv  + N_BSD;
    float* p_ov   = p_xa  + N_BSD;        // ov/oa contiguous -> [2048][768]
    float* p_oa   = p_ov  + N_BSD;
    float* p_h    = p_oa  + N_BSD;        // [2048][512]

    const int nBlk = (int)(N_BSD / 256);

    cudaFuncSetAttribute(bilinear3_kernel,
                         cudaFuncAttributeMaxDynamicSharedMemorySize, BIL3_SMEM_BYTES);

    fuse_bias_kernel<<<1, 256>>>(mmfaB, p_bf);
    wconv_kernel<<<16384, 256>>>(bilW, p_Wh);
    float* p_b45 = p_bf;
    float* p_b67 = p_bf + 256;

    auto run_mmfa = [&](const float* xv, const float* xa,
                        const float* mv, const float* ma, float* o1, float* o2) {
        launch_mma(xv, mmfaW + 0 * 65536, mmfaB + 0 * 256, p_qkv, M3, 512, Dd, 8,
                   mmfaW + 2 * 65536, 256, mmfaB + 2 * 256);
        launch_mma(xa, mmfaW + 1 * 65536, mmfaB + 1 * 256, p_qka, M3, 512, Dd, 8,
                   mmfaW + 3 * 65536, 256, mmfaB + 3 * 256);
        attn_kernel<<<Bn, 256>>>(xv, xa, p_qkv, p_qka, p_cat1, p_cat2);
        launch_mma(p_cat1, mmfaW + 4 * 65536, p_b45, p_cva, M3, Dd, 512, 4,
                   mmfaW + 5 * 65536, 256, nullptr, p_cat1, 512, 256);
        launch_mma(p_cat2, mmfaW + 6 * 65536, p_b67, p_cav, M3, Dd, 512, 4,
                   mmfaW + 7 * 65536, 256, nullptr, p_cat2, 512, 256);
        dim3 bg(24, 4, 4);
        bilinear3_kernel<<<bg, 256, BIL3_SMEM_BYTES>>>(p_cva, p_cav, p_Wh, p_bp);
        bil_finish_kernel<<<nBlk, 256>>>(p_bp, xv, xa, t_c, mv, ma, o1, o2);
    };

    // encoders + multi-scale: fp32 SIMT (precision root)
    launch_gemm_f32(img,   vis_W, vis_b, p_vis, Bn, 1024, 4096, 1);
    launch_gemm_f32(audio, aud_W, aud_b, p_aud, Bn, 1024, 1024, 1);
    launch_gemm_f32(p_vis, msv_W, msv_b, p_vms, Bn, SD, 1024, 1);
    launch_gemm_f32(p_aud, msa_W, msa_b, p_ams, Bn, SD, 1024, 1);

    // MMfa 1: xv2 = M1*vms, xa2 = M1*ams
    run_mmfa(p_vms, p_ams, p_vms, p_ams, p_xv, p_xa);
    // MMfa 2: ov = M2*vms, oa = M2*ams
    run_mmfa(p_xv, p_xa, p_vms, p_ams, p_ov, p_oa);

    float* out = (float*)d_out;
    float* fv = out;
    float* fa = out + (size_t)Bn * LAT;
    float* pv = fa + (size_t)Bn * LAT;
    float* pa = pv + (size_t)Bn * 10;

    launch_mma(p_ov, out_W1, out_b1, p_h, 2 * Bn, OUT1, SD, 1);
    launch_mma(p_h,  out_W2, out_b2, fv,  2 * Bn, LAT, OUT1, 0);

    cls_kernel<<<Bn / 8, 256>>>(fv, clsvW1, clsvW2, pv);
    cls_kernel<<<Bn / 8, 256>>>(fa, clsaW1, clsaW2, pa);
}

// round 7
// speedup vs baseline: 1.1281x; 1.0506x over previous
#include <cuda_runtime.h>
#include <cuda_fp16.h>
#include <math.h>
#include <stdint.h>

// ---------------- problem constants ----------------
static constexpr int Bn   = 1024;
static constexpr int M3   = 3072;   // B*S
static constexpr int Dd   = 256;
static constexpr int SD   = 768;
static constexpr int OUT1 = 512;
static constexpr int LAT  = 128;

static constexpr size_t N_BE  = (size_t)Bn * 1024;
static constexpr size_t N_BSD = (size_t)M3 * Dd;     // 786432

__device__ float g_scratch[2 * N_BE + 22 * N_BSD + (size_t)Bn * OUT1];
__device__ float g_bias_fused[512];            // [0:256)=b4+b5, [256:512)=b6+b7
__device__ __half g_Wh[16777216];              // bil_W in fp16 (32MB)

__device__ __forceinline__ float sigm(float x) { return 1.0f / (1.0f + expf(-x)); }

__device__ __forceinline__ unsigned tf32r(float x) {
    unsigned r;
    asm("cvt.rna.tf32.f32 %0, %1;" : "=r"(r) : "f"(x));
    return r;
}

__device__ __forceinline__ void mma_tf32(float& c0, float& c1, float& c2, float& c3,
                                         unsigned a0, unsigned a1, unsigned a2, unsigned a3,
                                         unsigned b0, unsigned b1) {
    asm("mma.sync.aligned.m16n8k8.row.col.f32.tf32.tf32.f32 "
        "{%0,%1,%2,%3}, {%4,%5,%6,%7}, {%8,%9}, {%0,%1,%2,%3};"
        : "+f"(c0), "+f"(c1), "+f"(c2), "+f"(c3)
        : "r"(a0), "r"(a1), "r"(a2), "r"(a3), "r"(b0), "r"(b1));
}

__device__ __forceinline__ void mma_f16(float& c0, float& c1, float& c2, float& c3,
                                        unsigned a0, unsigned a1, unsigned a2, unsigned a3,
                                        unsigned b0, unsigned b1) {
    asm("mma.sync.aligned.m16n8k16.row.col.f32.f16.f16.f32 "
        "{%0,%1,%2,%3}, {%4,%5,%6,%7}, {%8,%9}, {%0,%1,%2,%3};"
        : "+f"(c0), "+f"(c1), "+f"(c2), "+f"(c3)
        : "r"(a0), "r"(a1), "r"(a2), "r"(a3), "r"(b0), "r"(b1));
}

// ---------------- helpers ----------------
__global__ void fuse_bias_kernel(const float* __restrict__ b, float* __restrict__ o)
{
    int i = threadIdx.x;
    o[i]       = b[4 * 256 + i] + b[5 * 256 + i];
    o[256 + i] = b[6 * 256 + i] + b[7 * 256 + i];
}

__global__ void wconv_kernel(const float* __restrict__ W, __half* __restrict__ Wh)
{
    size_t i = ((size_t)blockIdx.x * 256 + threadIdx.x) * 4;
    float4 v = *(const float4*)(W + i);
    *(__half2*)(Wh + i)     = __floats2half2_rn(v.x, v.y);
    *(__half2*)(Wh + i + 2) = __floats2half2_rn(v.z, v.w);
}

// ---------------- fp32 SIMT GEMM, z-batched: 128x64 tile, 256 threads ----------
struct GB32 {
    const float* A[2]; const float* W[2]; const float* b[2]; float* C[2]; int K[2];
};

__global__ void __launch_bounds__(256) gemm_kernel(GB32 P, int M, int N, int flags)
{
    __shared__ __align__(16) float As[16][132];
    __shared__ __align__(16) float Ws[16][68];
    const int z = blockIdx.z;
    const float* A = P.A[z];
    const float* W = P.W[z];
    const float* bias = P.b[z];
    float* C = P.C[z];
    const int K = P.K[z];

    const int tid = threadIdx.x;
    const int tx = tid & 15, ty = tid >> 4;
    const int m0 = blockIdx.y * 128, n0 = blockIdx.x * 64;
    const int lrow = tid >> 2, lk = (tid & 3) << 2;

    const float* Ag0 = A + (size_t)(m0 + lrow) * K + lk;
    const float* Ag1 = A + (size_t)(m0 + lrow + 64) * K + lk;
    const float* Wg  = W + (size_t)(n0 + lrow) * K + lk;

    float acc[8][4] = {};
    for (int kt = 0; kt < K; kt += 16) {
        float4 a0 = *(const float4*)(Ag0 + kt);
        float4 a1 = *(const float4*)(Ag1 + kt);
        float4 w0 = *(const float4*)(Wg + kt);
        As[lk + 0][lrow] = a0.x; As[lk + 1][lrow] = a0.y;
        As[lk + 2][lrow] = a0.z; As[lk + 3][lrow] = a0.w;
        As[lk + 0][lrow + 64] = a1.x; As[lk + 1][lrow + 64] = a1.y;
        As[lk + 2][lrow + 64] = a1.z; As[lk + 3][lrow + 64] = a1.w;
        Ws[lk + 0][lrow] = w0.x; Ws[lk + 1][lrow] = w0.y;
        Ws[lk + 2][lrow] = w0.z; Ws[lk + 3][lrow] = w0.w;
        __syncthreads();
#pragma unroll
        for (int k = 0; k < 16; k++) {
            float ar[8];
            *(float4*)&ar[0] = *(const float4*)&As[k][ty * 8];
            *(float4*)&ar[4] = *(const float4*)&As[k][ty * 8 + 4];
            float4 b = *(const float4*)&Ws[k][tx * 4];
#pragma unroll
            for (int i = 0; i < 8; i++) {
                acc[i][0] = fmaf(ar[i], b.x, acc[i][0]);
                acc[i][1] = fmaf(ar[i], b.y, acc[i][1]);
                acc[i][2] = fmaf(ar[i], b.z, acc[i][2]);
                acc[i][3] = fmaf(ar[i], b.w, acc[i][3]);
            }
        }
        __syncthreads();
    }
#pragma unroll
    for (int i = 0; i < 8; i++) {
        int row = m0 + ty * 8 + i;
#pragma unroll
        for (int j = 0; j < 4; j++) {
            int col = n0 + tx * 4 + j;
            float v = acc[i][j] + bias[col];
            if (flags & 1) v = fmaxf(v, 0.0f);
            C[(size_t)row * N + col] = v;
        }
    }
}

// ---------------- tf32 tensor GEMM, z-batched: K-split or N-split + fused epilogue ----
// flags: bit0 relu ; bit2 sigmul: out = sigm(v * E[row*eld + eoff + col]) ; bit3 N-split
struct GB {
    const float* A[2]; const float* W[2]; const float* W2[2];
    const float* b1[2]; const float* b2[2]; const float* E[2]; float* C[2];
};

__global__ void __launch_bounds__(128) mma_gemm_kernel(
    GB P, int M, int N, int K, int Kx, int flags, int eld, int eoff)
{
    __shared__ float As[16][72];
    __shared__ float Ws[16][72];
    const int z = blockIdx.z;
    const float* A = P.A[z];
    const float* W = P.W[z];
    const float* W2 = P.W2[z];
    const float* bias = P.b1[z];
    const float* bias2 = P.b2[z];
    const float* E = P.E[z];
    float* C = P.C[z];

    const int tid = threadIdx.x;
    const int lane = tid & 31, wid = tid >> 5;
    const int wm = wid >> 1, wn = wid & 1;
    const int m0 = blockIdx.y * 64, n0 = blockIdx.x * 64;
    const int c4 = lane & 3, lr = lane >> 2;
    const int Kb = K - Kx;
    const bool nsplit = (flags & 8) != 0;

    float c[2][4][4];
#pragma unroll
    for (int mt = 0; mt < 2; mt++)
#pragma unroll
        for (int nt = 0; nt < 4; nt++)
#pragma unroll
            for (int e = 0; e < 4; e++) c[mt][nt][e] = 0.0f;

    const int lrow = tid >> 2, lsq = tid & 3;
    float4 pa[2], pw[2];
    {
        int k = lsq * 4;
#pragma unroll
        for (int u = 0; u < 2; u++) {
            int row = lrow + u * 32;
            pa[u] = *(const float4*)(A + (size_t)(m0 + row) * K + k);
            const float* ws;
            if (nsplit) {
                int n = n0 + row;
                ws = (n < Kx) ? (W + (size_t)n * K + k) : (W2 + (size_t)(n - Kx) * K + k);
            } else {
                ws = (k < Kx) ? (W + (size_t)(n0 + row) * Kx + k)
                              : (W2 + (size_t)(n0 + row) * Kb + (k - Kx));
            }
            pw[u] = *(const float4*)ws;
        }
    }

    const int ktiles = K >> 4;
    for (int kt = 0; kt < ktiles; kt++) {
#pragma unroll
        for (int u = 0; u < 2; u++) {
            int row = lrow + u * 32;
            As[lsq * 4 + 0][row] = __uint_as_float(tf32r(pa[u].x));
            As[lsq * 4 + 1][row] = __uint_as_float(tf32r(pa[u].y));
            As[lsq * 4 + 2][row] = __uint_as_float(tf32r(pa[u].z));
            As[lsq * 4 + 3][row] = __uint_as_float(tf32r(pa[u].w));
            Ws[lsq * 4 + 0][row] = __uint_as_float(tf32r(pw[u].x));
            Ws[lsq * 4 + 1][row] = __uint_as_float(tf32r(pw[u].y));
            Ws[lsq * 4 + 2][row] = __uint_as_float(tf32r(pw[u].z));
            Ws[lsq * 4 + 3][row] = __uint_as_float(tf32r(pw[u].w));
        }
        __syncthreads();
        if (kt + 1 < ktiles) {
            int k = (kt + 1) * 16 + lsq * 4;
#pragma unroll
            for (int u = 0; u < 2; u++) {
                int row = lrow + u * 32;
                pa[u] = *(const float4*)(A + (size_t)(m0 + row) * K + k);
                const float* ws;
                if (nsplit) {
                    int n = n0 + row;
                    ws = (n < Kx) ? (W + (size_t)n * K + k) : (W2 + (size_t)(n - Kx) * K + k);
                } else {
                    ws = (k < Kx) ? (W + (size_t)(n0 + row) * Kx + k)
                                  : (W2 + (size_t)(n0 + row) * Kb + (k - Kx));
                }
                pw[u] = *(const float4*)ws;
            }
        }
#pragma unroll
        for (int kk = 0; kk < 16; kk += 8) {
            unsigned a[2][4];
#pragma unroll
            for (int mt = 0; mt < 2; mt++) {
                int rb = wm * 32 + mt * 16 + lr;
                a[mt][0] = __float_as_uint(As[kk + c4][rb]);
                a[mt][1] = __float_as_uint(As[kk + c4][rb + 8]);
                a[mt][2] = __float_as_uint(As[kk + c4 + 4][rb]);
                a[mt][3] = __float_as_uint(As[kk + c4 + 4][rb + 8]);
            }
#pragma unroll
            for (int nt = 0; nt < 4; nt++) {
                int nb = wn * 32 + nt * 8 + lr;
                unsigned b0 = __float_as_uint(Ws[kk + c4][nb]);
                unsigned b1 = __float_as_uint(Ws[kk + c4 + 4][nb]);
#pragma unroll
                for (int mt = 0; mt < 2; mt++)
                    mma_tf32(c[mt][nt][0], c[mt][nt][1], c[mt][nt][2], c[mt][nt][3],
                             a[mt][0], a[mt][1], a[mt][2], a[mt][3], b0, b1);
            }
        }
        __syncthreads();
    }

#pragma unroll
    for (int mt = 0; mt < 2; mt++) {
#pragma unroll
        for (int nt = 0; nt < 4; nt++) {
            int row = m0 + wm * 32 + mt * 16 + lr;
            int col = n0 + wn * 32 + nt * 8 + c4 * 2;
#pragma unroll
            for (int e = 0; e < 4; e++) {
                int rr = row + (e >> 1) * 8;
                int cc = col + (e & 1);
                float bv = nsplit ? ((cc < Kx) ? bias[cc] : bias2[cc - Kx]) : bias[cc];
                float v = c[mt][nt][e] + bv;
                if (flags & 1) v = fmaxf(v, 0.0f);
                if (flags & 4) v = sigm(v * E[(size_t)rr * eld + eoff + cc]);
                C[(size_t)rr * N + cc] = v;
            }
        }
    }
}

// ---------------- fp16 bilinear v4: 128 thr, warp tile 64x32, single-sync pipeline ----
// grid (24, 4, 4): r-block 128, o-block 64, i-range 64. 4 warps (2m x 2n), mt=4.
// smem: s_cav [128][264] fp16 + s_W [2][64][72] fp16 = 86016 B -> 2 blocks/SM
static constexpr int BIL4_SMEM_BYTES = (128 * 264 + 2 * 64 * 72) * 2;

__global__ void __launch_bounds__(128) bilinear4_kernel(
    const float* __restrict__ cva, const float* __restrict__ cav,
    const __half* __restrict__ Wh, float* __restrict__ part)
{
    extern __shared__ __half sh[];
    __half* s_cav = sh;                // [128][264]
    __half* s_W   = sh + 128 * 264;    // [2][64][72]

    const int tid = threadIdx.x;
    const int lane = tid & 31, wid = tid >> 5;
    const int wm = wid & 1, wn = wid >> 1;   // 2m(64) x 2n(32)
    const int g = lane >> 2, q = lane & 3;
    const int r0 = blockIdx.x * 128, o0 = blockIdx.y * 64;
    const int iBase = blockIdx.z * 64;

    // load cav rows [r0, r0+128) -> fp16 smem
    for (int f = tid; f < 8192; f += 128) {
        int row = f >> 6, q4 = f & 63;
        float4 w = *(const float4*)(cav + (size_t)(r0 + row) * 256 + q4 * 4);
        __half* d = s_cav + row * 264 + q4 * 4;
        *(__half2*)(d)     = __floats2half2_rn(w.x, w.y);
        *(__half2*)(d + 2) = __floats2half2_rn(w.z, w.w);
    }

    float c[4][4][4];
#pragma unroll
    for (int mt = 0; mt < 4; mt++)
#pragma unroll
        for (int nt = 0; nt < 4; nt++)
#pragma unroll
            for (int e = 0; e < 4; e++) c[mt][nt][e] = 0.0f;

    // cp.async W tile: 64 o x 64 j halves = 8KB = 512 x 16B chunks, 4 per thread
    auto issue_tile = [&](int it) {
        int i = iBase + (it >> 2), h = it & 3;
        __half* dst0 = s_W + (it & 1) * 64 * 72;
#pragma unroll
        for (int u = 0; u < 4; u++) {
            int cidx = tid + 128 * u;          // 0..511
            int o = cidx >> 3, ch = cidx & 7;
            const __half* src = Wh + (size_t)(o0 + o) * 65536 + (size_t)i * 256 + h * 64 + ch * 8;
            unsigned sa = (unsigned)__cvta_generic_to_shared(dst0 + o * 72 + ch * 8);
            asm volatile("cp.async.cg.shared.global [%0], [%1], 16;" :: "r"(sa), "l"(src));
        }
        asm volatile("cp.async.commit_group;");
    };

    issue_tile(0);

    const int rb = wm * 64 + g;
    const float* cvaB = cva + (size_t)r0 * 256;

    for (int it = 0; it < 256; it++) {
        asm volatile("cp.async.wait_group 0;");
        __syncthreads();   // tile(it) + s_cav visible; compute(it-1) done in all threads
        if (it + 1 < 256) issue_tile(it + 1);

        const __half* wbuf = s_W + (it & 1) * 64 * 72;
        const int ig = iBase + (it >> 2);
        const int h = it & 3;
        __half2 s[8];
#pragma unroll
        for (int mt = 0; mt < 4; mt++) {
            s[2 * mt]     = __half2half2(__float2half_rn(cvaB[(size_t)(rb + mt * 16) * 256 + ig]));
            s[2 * mt + 1] = __half2half2(__float2half_rn(cvaB[(size_t)(rb + mt * 16 + 8) * 256 + ig]));
        }

#pragma unroll
        for (int jc = 0; jc < 4; jc++) {
            const int jlo = h * 64 + jc * 16 + 2 * q;
            const int jhi = jlo + 8;
            __half2 a[4][4];
#pragma unroll
            for (int mt = 0; mt < 4; mt++) {
                int r1 = rb + mt * 16, r2 = r1 + 8;
                a[mt][0] = __hmul2(*(__half2*)&s_cav[r1 * 264 + jlo], s[2 * mt]);
                a[mt][1] = __hmul2(*(__half2*)&s_cav[r2 * 264 + jlo], s[2 * mt + 1]);
                a[mt][2] = __hmul2(*(__half2*)&s_cav[r1 * 264 + jhi], s[2 * mt]);
                a[mt][3] = __hmul2(*(__half2*)&s_cav[r2 * 264 + jhi], s[2 * mt + 1]);
            }
            const int kloc = jc * 16;
#pragma unroll
            for (int nt = 0; nt < 4; nt++) {
                int oc = wn * 32 + nt * 8 + g;
                unsigned b0 = *(const unsigned*)&wbuf[oc * 72 + kloc + 2 * q];
                unsigned b1 = *(const unsigned*)&wbuf[oc * 72 + kloc + 2 * q + 8];
#pragma unroll
                for (int mt = 0; mt < 4; mt++)
                    mma_f16(c[mt][nt][0], c[mt][nt][1], c[mt][nt][2], c[mt][nt][3],
                            *(unsigned*)&a[mt][0], *(unsigned*)&a[mt][1],
                            *(unsigned*)&a[mt][2], *(unsigned*)&a[mt][3], b0, b1);
            }
        }
        // no trailing sync: next iter's sync (after wait) gates buffer reuse
    }

    float* P = part + (size_t)blockIdx.z * N_BSD;
#pragma unroll
    for (int mt = 0; mt < 4; mt++) {
#pragma unroll
        for (int nt = 0; nt < 4; nt++) {
            int row = r0 + wm * 64 + mt * 16 + g;
            int col = o0 + wn * 32 + nt * 8 + q * 2;
            float* d0 = P + (size_t)row * 256 + col;
            float* d1 = P + (size_t)(row + 8) * 256 + col;
            d0[0] = c[mt][nt][0]; d0[1] = c[mt][nt][1];
            d1[0] = c[mt][nt][2]; d1[1] = c[mt][nt][3];
        }
    }
}

// finish: j = sigm(sum partials); m = tc*j*xv + (1-j)*xa; o1 = m*mv; o2 = m*ma
__global__ void bil_finish_kernel(const float* __restrict__ part,
                                  const float* __restrict__ xv, const float* __restrict__ xa,
                                  const float* __restrict__ tcp,
                                  const float* __restrict__ mv, const float* __restrict__ ma,
                                  float* __restrict__ o1, float* __restrict__ o2)
{
    int i = blockIdx.x * 256 + threadIdx.x;
    float s = part[i] + part[i + N_BSD] + part[i + 2 * N_BSD] + part[i + 3 * N_BSD];
    float j = sigm(s);
    float m = (*tcp) * j * xv[i] + (1.0f - j) * xa[i];
    o1[i] = m * mv[i];
    o2[i] = m * ma[i];
}

// ---------------- attention ----------------
__global__ void __launch_bounds__(256) attn_kernel(
    const float* __restrict__ xv, const float* __restrict__ xa,
    const float* __restrict__ qkv_v, const float* __restrict__ qkv_a,
    float* __restrict__ cat1, float* __restrict__ cat2)
{
    __shared__ float s_x[2][3][256];
    __shared__ float s_q[2][3][256];
    __shared__ float s_k[2][3][256];
    __shared__ float s_sc[4][3][3];
    const int tid = threadIdx.x;
    const size_t base = (size_t)blockIdx.x * 768;
    const size_t base2 = (size_t)blockIdx.x * 1536;
    const size_t qbase = (size_t)blockIdx.x * 3 * 512;

    float* fx = &s_x[0][0][0];
    float* fq = &s_q[0][0][0];
    float* fk = &s_k[0][0][0];
    for (int idx = tid; idx < 768; idx += 256) {
        int s3 = idx >> 8, d = idx & 255;
        size_t qoff = qbase + (size_t)s3 * 512 + d;
        fx[idx] = xv[base + idx]; fx[768 + idx] = xa[base + idx];
        fq[idx] = qkv_v[qoff];        fq[768 + idx] = qkv_a[qoff];
        fk[idx] = qkv_v[qoff + 256];  fk[768 + idx] = qkv_a[qoff + 256];
    }
    __syncthreads();

    const int w = tid >> 5, lane = tid & 31;
    for (int task = w; task < 36; task += 8) {
        int type = task / 9, rem = task % 9, s3 = rem / 3, t3 = rem % 3;
        int qsel = type >> 1;
        int ksel = (type == 0 || type == 3) ? 1 : 0;
        float sum = 0.0f;
        for (int d = lane; d < 256; d += 32) sum += s_q[qsel][s3][d] * s_k[ksel][t3][d];
#pragma unroll
        for (int off = 16; off; off >>= 1) sum += __shfl_down_sync(0xffffffffu, sum, off);
        if (lane == 0) s_sc[type][s3][t3] = sum;
    }
    __syncthreads();

    if (tid < 12) {
        int type = tid / 3, s3 = tid % 3;
        float a = s_sc[type][s3][0], b = s_sc[type][s3][1], c = s_sc[type][s3][2];
        float m = fmaxf(a, fmaxf(b, c));
        float ea = expf(a - m), eb = expf(b - m), ec = expf(c - m);
        float inv = 0.0625f / (ea + eb + ec);
        s_sc[type][s3][0] = ea * inv; s_sc[type][s3][1] = eb * inv; s_sc[type][s3][2] = ec * inv;
    }
    __syncthreads();

    for (int idx = tid; idx < 3072; idx += 256) {
        int type = idx / 768, rem = idx % 768;
        int s3 = rem >> 8, d = rem & 255;
        int xsel = (type == 0 || type == 3) ? 1 : 0;
        float v = s_sc[type][s3][0] * s_x[xsel][0][d]
                + s_sc[type][s3][1] * s_x[xsel][1][d]
                + s_sc[type][s3][2] * s_x[xsel][2][d];
        float* dst = (type < 2) ? cat1 : cat2;
        dst[base2 + (size_t)s3 * 512 + ((type & 1) ? 256 : 0) + d] = v;
    }
}

// ---------------- classifier ----------------
__global__ void __launch_bounds__(256) cls_kernel(
    const float* __restrict__ F, const float* __restrict__ W1,
    const float* __restrict__ W2, float* __restrict__ P)
{
    __shared__ float s_f[8][128];
    __shared__ float s_w1[32][129];
    __shared__ float s_w2[320];
    __shared__ float s_h[8][32];
    const int tid = threadIdx.x;
    const int r0 = blockIdx.x * 8;
    for (int idx = tid; idx < 1024; idx += 256) s_f[idx >> 7][idx & 127] = F[(size_t)r0 * 128 + idx];
    for (int idx = tid; idx < 4096; idx += 256) s_w1[idx >> 7][idx & 127] = W1[idx];
    for (int idx = tid; idx < 320; idx += 256) s_w2[idx] = W2[idx];
    __syncthreads();
    const int w = tid >> 5, lane = tid & 31;
    float h = 0.0f;
#pragma unroll 8
    for (int d = 0; d < 128; d++) h = fmaf(s_f[w][d], s_w1[lane][d], h);
    s_h[w][lane] = fmaxf(h, 0.0f);
    __syncwarp();
    if (lane < 10) {
        float p = 0.0f;
#pragma unroll
        for (int k = 0; k < 32; k++) p = fmaf(s_h[w][k], s_w2[lane * 32 + k], p);
        P[(size_t)(r0 + w) * 10 + lane] = p;
    }
}

// ---------------- host ----------------
extern "C" void kernel_launch(void* const* d_in, const int* in_sizes, int n_in,
                              void* d_out, int out_size)
{
    const float* img    = (const float*)d_in[0];
    const float* audio  = (const float*)d_in[1];
    const float* vis_W  = (const float*)d_in[2];
    const float* vis_b  = (const float*)d_in[3];
    const float* aud_W  = (const float*)d_in[4];
    const float* aud_b  = (const float*)d_in[5];
    const float* msv_W  = (const float*)d_in[6];
    const float* msv_b  = (const float*)d_in[7];
    const float* msa_W  = (const float*)d_in[8];
    const float* msa_b  = (const float*)d_in[9];
    const float* mmfaW  = (const float*)d_in[10];
    const float* mmfaB  = (const float*)d_in[11];
    const float* bilW   = (const float*)d_in[12];
    const float* t_c    = (const float*)d_in[13];
    const float* out_W1 = (const float*)d_in[14];
    const float* out_b1 = (const float*)d_in[15];
    const float* out_W2 = (const float*)d_in[16];
    const float* out_b2 = (const float*)d_in[17];
    const float* clsvW1 = (const float*)d_in[18];
    const float* clsvW2 = (const float*)d_in[19];
    const float* clsaW1 = (const float*)d_in[20];
    const float* clsaW2 = (const float*)d_in[21];

    float* S = nullptr;
    cudaGetSymbolAddress((void**)&S, g_scratch);
    float* p_bf = nullptr;
    cudaGetSymbolAddress((void**)&p_bf, g_bias_fused);
    __half* p_Wh = nullptr;
    cudaGetSymbolAddress((void**)&p_Wh, g_Wh);

    float* p_vis  = S;
    float* p_aud  = p_vis + N_BE;
    float* p_vms  = p_aud + N_BE;
    float* p_ams  = p_vms + N_BSD;
    float* p_qkv  = p_ams + N_BSD;        // [3072][512] (qv | kv)
    float* p_qka  = p_qkv + 2 * N_BSD;    // [3072][512] (qa | ka)
    float* p_cat1 = p_qka + 2 * N_BSD;    // [3072][512]
    float* p_cat2 = p_cat1 + 2 * N_BSD;   // [3072][512]
    float* p_cva  = p_cat2 + 2 * N_BSD;
    float* p_cav  = p_cva + N_BSD;
    float* p_bp   = p_cav + N_BSD;        // 4 x [3072][256]
    float* p_xv   = p_bp  + 4 * N_BSD;
    float* p_xa   = p_xv  + N_BSD;
    float* p_ov   = p_xa  + N_BSD;        // ov/oa contiguous -> [2048][768]
    float* p_oa   = p_ov  + N_BSD;
    float* p_h    = p_oa  + N_BSD;        // [2048][512]

    const int nBlk = (int)(N_BSD / 256);

    cudaFuncSetAttribute(bilinear4_kernel,
                         cudaFuncAttributeMaxDynamicSharedMemorySize, BIL4_SMEM_BYTES);

    fuse_bias_kernel<<<1, 256>>>(mmfaB, p_bf);
    wconv_kernel<<<16384, 256>>>(bilW, p_Wh);
    float* p_b45 = p_bf;
    float* p_b67 = p_bf + 256;

    auto run_mmfa = [&](const float* xv, const float* xa,
                        const float* mv, const float* ma, float* o1, float* o2) {
        // q|k for both modalities in ONE launch (z-batched, N-split)
        GB qk;
        qk.A[0] = xv;  qk.W[0] = mmfaW + 0 * 65536; qk.W2[0] = mmfaW + 2 * 65536;
        qk.b1[0] = mmfaB + 0 * 256; qk.b2[0] = mmfaB + 2 * 256; qk.E[0] = xv;  qk.C[0] = p_qkv;
        qk.A[1] = xa;  qk.W[1] = mmfaW + 1 * 65536; qk.W2[1] = mmfaW + 3 * 65536;
        qk.b1[1] = mmfaB + 1 * 256; qk.b2[1] = mmfaB + 3 * 256; qk.E[1] = xa;  qk.C[1] = p_qka;
        mma_gemm_kernel<<<dim3(512 / 64, M3 / 64, 2), 128>>>(qk, M3, 512, Dd, 256, 8, 0, 0);

        attn_kernel<<<Bn, 256>>>(xv, xa, p_qkv, p_qka, p_cat1, p_cat2);

        // cva|cav in ONE launch (z-batched, K-split, sigmul epilogue)
        GB cc;
        cc.A[0] = p_cat1; cc.W[0] = mmfaW + 4 * 65536; cc.W2[0] = mmfaW + 5 * 65536;
        cc.b1[0] = p_b45; cc.b2[0] = p_b45; cc.E[0] = p_cat1; cc.C[0] = p_cva;
        cc.A[1] = p_cat2; cc.W[1] = mmfaW + 6 * 65536; cc.W2[1] = mmfaW + 7 * 65536;
        cc.b1[1] = p_b67; cc.b2[1] = p_b67; cc.E[1] = p_cat2; cc.C[1] = p_cav;
        mma_gemm_kernel<<<dim3(256 / 64, M3 / 64, 2), 128>>>(cc, M3, Dd, 512, 256, 4, 512, 256);

        bilinear4_kernel<<<dim3(24, 4, 4), 128, BIL4_SMEM_BYTES>>>(p_cva, p_cav, p_Wh, p_bp);
        bil_finish_kernel<<<nBlk, 256>>>(p_bp, xv, xa, t_c, mv, ma, o1, o2);
    };

    // encoders (vis||aud, different K per z) + multi-scale (z-batched), fp32 SIMT
    {
        GB32 e;
        e.A[0] = img;   e.W[0] = vis_W; e.b[0] = vis_b; e.C[0] = p_vis; e.K[0] = 4096;
        e.A[1] = audio; e.W[1] = aud_W; e.b[1] = aud_b; e.C[1] = p_aud; e.K[1] = 1024;
        gemm_kernel<<<dim3(16, 8, 2), 256>>>(e, Bn, 1024, 1);

        GB32 m;
        m.A[0] = p_vis; m.W[0] = msv_W; m.b[0] = msv_b; m.C[0] = p_vms; m.K[0] = 1024;
        m.A[1] = p_aud; m.W[1] = msa_W; m.b[1] = msa_b; m.C[1] = p_ams; m.K[1] = 1024;
        gemm_kernel<<<dim3(12, 8, 2), 256>>>(m, Bn, SD, 1);
    }

    // MMfa 1: xv2 = M1*vms, xa2 = M1*ams ; MMfa 2: ov = M2*vms, oa = M2*ams
    run_mmfa(p_vms, p_ams, p_vms, p_ams, p_xv, p_xa);
    run_mmfa(p_xv, p_xa, p_vms, p_ams, p_ov, p_oa);

    float* out = (float*)d_out;
    float* fv = out;
    float* fa = out + (size_t)Bn * LAT;
    float* pv = fa + (size_t)Bn * LAT;
    float* pa = pv + (size_t)Bn * 10;

    // out_layer M-batched over (ov||oa) -> (fv||fa) ; tf32 kernel with z=1
    {
        GB o1;
        o1.A[0] = o1.A[1] = p_ov; o1.W[0] = o1.W[1] = out_W1; o1.W2[0] = o1.W2[1] = out_W1;
        o1.b1[0] = o1.b1[1] = out_b1; o1.b2[0] = o1.b2[1] = out_b1;
        o1.E[0] = o1.E[1] = p_ov; o1.C[0] = o1.C[1] = p_h;
        mma_gemm_kernel<<<dim3(OUT1 / 64, 2 * Bn / 64, 1), 128>>>(o1, 2 * Bn, OUT1, SD, SD, 1, 0, 0);

        GB o2;
        o2.A[0] = o2.A[1] = p_h; o2.W[0] = o2.W[1] = out_W2; o2.W2[0] = o2.W2[1] = out_W2;
        o2.b1[0] = o2.b1[1] = out_b2; o2.b2[0] = o2.b2[1] = out_b2;
        o2.E[0] = o2.E[1] = p_h; o2.C[0] = o2.C[1] = fv;
        mma_gemm_kernel<<<dim3(LAT / 64, 2 * Bn / 64, 1), 128>>>(o2, 2 * Bn, LAT, OUT1, OUT1, 0, 0, 0);
    }

    cls_kernel<<<Bn / 8, 256>>>(fv, clsvW1, clsvW2, pv);
    cls_kernel<<<Bn / 8, 256>>>(fa, clsaW1, clsaW2, pa);
}